// round 17
// baseline (speedup 1.0000x reference)
#include <cuda_runtime.h>
#include <cuda_bf16.h>
#include <cstdint>
#include <math.h>

typedef unsigned int u32;

#define NN 100000
#define EE 1600000
#define GG 1000
#define FF 16
#define DD 128
#define CC 100
#define KK 2
#define LL 3

#define SCB 512
#define NB  ((NN + SCB - 1) / SCB)
#define PAD2 68        // word pitch for 64-word rows -> conflict-free fragment loads

// ---------------- scratch ----------------
__device__ float g_dinv[NN];
__device__ u32   g_mb[(size_t)NN * 64];    // messages buffer A (bf16x2 packed)
__device__ u32   g_mb2[(size_t)NN * 64];   // messages buffer B
__device__ float g_pool[GG * CC];
__device__ float g_cnt[GG];
__device__ float g_wf[DD * FF];
__device__ int   g_cnti[NN];
__device__ int   g_rowptr[NN + 1];
__device__ int   g_cursor[NN];
__device__ int   g_bsum[NB];
__device__ int   g_csr[EE];

__device__ __forceinline__ float2 bf2f(u32 u) {
    __nv_bfloat162 b = *(__nv_bfloat162*)&u;
    return __bfloat1622float2(b);
}
__device__ __forceinline__ u32 f2bf2(float a, float b) {
    __nv_bfloat162 p = __floats2bfloat162_rn(a, b);
    return *(u32*)&p;
}
__device__ __forceinline__ void mma_bf16(float* d, u32 a0, u32 a1, u32 a2, u32 a3,
                                         u32 b0, u32 b1) {
    asm("mma.sync.aligned.m16n8k16.row.col.f32.bf16.bf16.f32 "
        "{%0,%1,%2,%3}, {%4,%5,%6,%7}, {%8,%9}, {%0,%1,%2,%3};"
        : "+f"(d[0]), "+f"(d[1]), "+f"(d[2]), "+f"(d[3])
        : "r"(a0), "r"(a1), "r"(a2), "r"(a3), "r"(b0), "r"(b1));
}

// ---------------- zero ----------------
__global__ void k_zero() {
    int i = blockIdx.x * blockDim.x + threadIdx.x;
    if (i < NN) g_cnti[i] = 0;
    if (i < GG * CC) g_pool[i] = 0.f;
    if (i < GG) g_cnt[i] = 0.f;
}

// ---------------- CSR build (+ batch counts fused) ----------------
__global__ void k_count(const int* __restrict__ dst, const int* __restrict__ batch) {
    int e = blockIdx.x * blockDim.x + threadIdx.x;
    if (e < EE) atomicAdd(&g_cnti[dst[e]], 1);
    if (e < NN) atomicAdd(&g_cnt[batch[e]], 1.0f);
}
__global__ void k_scan_part() {
    __shared__ int s[SCB];
    int t = threadIdx.x;
    int i = blockIdx.x * SCB + t;
    int v = (i < NN) ? g_cnti[i] : 0;
    s[t] = v;
    __syncthreads();
#pragma unroll
    for (int off = 1; off < SCB; off <<= 1) {
        int x = (t >= off) ? s[t - off] : 0;
        __syncthreads();
        s[t] += x;
        __syncthreads();
    }
    if (i < NN) g_rowptr[i] = s[t] - v;
    if (t == SCB - 1) g_bsum[blockIdx.x] = s[t];
}
__global__ void k_scan_bsum() {
    __shared__ int s[256];
    int t = threadIdx.x;
    int v = (t < NB) ? g_bsum[t] : 0;
    s[t] = v;
    __syncthreads();
#pragma unroll
    for (int off = 1; off < 256; off <<= 1) {
        int x = (t >= off) ? s[t - off] : 0;
        __syncthreads();
        s[t] += x;
        __syncthreads();
    }
    if (t < NB) g_bsum[t] = s[t] - v;
}
__global__ void k_scan_add() {
    int i = blockIdx.x * blockDim.x + threadIdx.x;
    if (i < NN) {
        int r = g_rowptr[i] + g_bsum[i / SCB];
        g_rowptr[i] = r;
        g_cursor[i] = r;
        g_dinv[i] = rsqrtf((float)(g_cnti[i] + 1));
    }
    if (i == 0) g_rowptr[NN] = EE;
}
__global__ void k_fill(const int* __restrict__ src, const int* __restrict__ dst) {
    int e = blockIdx.x * blockDim.x + threadIdx.x;
    if (e < EE) {
        int d = dst[e];
        int pos = atomicAdd(&g_cursor[d], 1);
        g_csr[pos] = src[e];
    }
}

// ---------------- fold: Wf = W1 @ We ----------------
__global__ void k_fold(const float* __restrict__ W1, const float* __restrict__ We) {
    __shared__ float we[DD * FF];
    int tid = threadIdx.x;
    for (int i = tid; i < DD * FF; i += 512) we[i] = We[i];
    __syncthreads();
    for (int i = tid; i < DD * FF; i += 512) {
        int d = i >> 4, f = i & 15;
        float s = 0.f;
#pragma unroll 8
        for (int k = 0; k < DD; k++) s += W1[d * DD + k] * we[k * FF + f];
        g_wf[i] = s;
    }
}

// ---------------- layer0 transform: m = dinv * (x @ Wf^T) -> g_mb ----------------
__global__ void k_gemm16(const float* __restrict__ x) {
    __shared__ float wt[FF * DD];
    __shared__ float xs[32 * FF];
    int tid = threadIdx.x;
    for (int idx = tid; idx < DD * FF; idx += 256) {
        int d = idx >> 4, f = idx & 15;
        wt[f * DD + d] = g_wf[idx];
    }
    int n0 = blockIdx.x * 32;
    for (int idx = tid; idx < 32 * FF; idx += 256) xs[idx] = x[(size_t)n0 * FF + idx];
    __syncthreads();

    int p = tid & 63;
    int nb = tid >> 6;
    int d0 = 2 * p;
#pragma unroll
    for (int it = 0; it < 8; it++) {
        int n = it * 4 + nb;
        float s0 = 0.f, s1 = 0.f;
#pragma unroll
        for (int f = 0; f < FF; f++) {
            float xv = xs[n * FF + f];
            s0 = fmaf(xv, wt[f * DD + d0], s0);
            s1 = fmaf(xv, wt[f * DD + d0 + 1], s1);
        }
        float sc = g_dinv[n0 + n];
        g_mb[(size_t)(n0 + n) * 64 + p] = f2bf2(s0 * sc, s1 * sc);
    }
}

// ---------------- gather-into-smem helper (warp-collective, one node) ----------------
#define ACC4(r) { \
    float2 q0 = bf2f((r).x), q1 = bf2f((r).y); \
    a0 += q0.x; a1 += q0.y; a2 += q1.x; a3 += q1.y; }

// Gathers node w's aggregated, relu'd h (4 floats per lane: cols 4*lane..4*lane+3)
__device__ __forceinline__ void gather_node(const uint2* __restrict__ M2, int w, int lane,
                                            float& a0, float& a1, float& a2, float& a3) {
    uint2 sr = M2[(size_t)w * 32 + lane];   // self loop
    a0 = 0.f; a1 = 0.f; a2 = 0.f; a3 = 0.f;
    ACC4(sr)
    int i = g_rowptr[w];
    int cnt = g_rowptr[w + 1] - i;
    while (cnt > 0) {
        int take = cnt > 32 ? 32 : cnt;
        int nb = (lane < take) ? g_csr[i + lane] : 0;
        int j = 0;
        for (; j + 8 <= take; j += 8) {
            int u0 = __shfl_sync(0xffffffffu, nb, j);
            int u1 = __shfl_sync(0xffffffffu, nb, j + 1);
            int u2 = __shfl_sync(0xffffffffu, nb, j + 2);
            int u3 = __shfl_sync(0xffffffffu, nb, j + 3);
            int u4 = __shfl_sync(0xffffffffu, nb, j + 4);
            int u5 = __shfl_sync(0xffffffffu, nb, j + 5);
            int u6 = __shfl_sync(0xffffffffu, nb, j + 6);
            int u7 = __shfl_sync(0xffffffffu, nb, j + 7);
            uint2 r0 = M2[(size_t)u0 * 32 + lane];
            uint2 r1 = M2[(size_t)u1 * 32 + lane];
            uint2 r2 = M2[(size_t)u2 * 32 + lane];
            uint2 r3 = M2[(size_t)u3 * 32 + lane];
            uint2 r4 = M2[(size_t)u4 * 32 + lane];
            uint2 r5 = M2[(size_t)u5 * 32 + lane];
            uint2 r6 = M2[(size_t)u6 * 32 + lane];
            uint2 r7 = M2[(size_t)u7 * 32 + lane];
            ACC4(r0) ACC4(r1) ACC4(r2) ACC4(r3)
            ACC4(r4) ACC4(r5) ACC4(r6) ACC4(r7)
        }
        for (; j < take; j++) {
            int u = __shfl_sync(0xffffffffu, nb, j);
            uint2 r = M2[(size_t)u * 32 + lane];
            ACC4(r)
        }
        i += take;
        cnt -= take;
    }
    float sc = g_dinv[w];
    a0 = fmaxf(a0 * sc, 0.f);
    a1 = fmaxf(a1 * sc, 0.f);
    a2 = fmaxf(a2 * sc, 0.f);
    a3 = fmaxf(a3 * sc, 0.f);
}

// ---------------- fused gather + GEMM: Mout = dinv * (relu-gather(Min) @ W^T) ----------------
// sel=0: Min=g_mb, Mout=g_mb2 ; sel=1: Min=g_mb2, Mout=g_mb
#define GE_SMEM (2 * DD * PAD2 * 4)
__global__ void __launch_bounds__(256, 2) k_fused_gemm(const float* __restrict__ W, int sel) {
    const u32* Min = sel ? g_mb2 : g_mb;
    u32* Mout      = sel ? g_mb  : g_mb2;
    extern __shared__ u32 sm[];
    u32* Ws = sm;                 // [128][PAD2] bf16x2 words (64 used)
    u32* hs = sm + DD * PAD2;     // [128][PAD2]
    int tid = threadIdx.x;
    int warp = tid >> 5, lane = tid & 31;
    int n0 = blockIdx.x * 128;

    // stage W as bf16
    for (int idx = tid; idx < DD * 64; idx += 256) {
        int r = idx >> 6, w = idx & 63;
        float2 wv = *(const float2*)&W[r * DD + 2 * w];
        Ws[r * PAD2 + w] = f2bf2(wv.x, wv.y);
    }

    // gather phase: warp handles 16 rows of the tile
    const uint2* M2 = (const uint2*)Min;
    for (int nn = 0; nn < 16; nn++) {
        int row = warp * 16 + nn;
        int w = n0 + row;
        float a0 = 0.f, a1 = 0.f, a2 = 0.f, a3 = 0.f;
        if (w < NN) gather_node(M2, w, lane, a0, a1, a2, a3);
        hs[row * PAD2 + 2 * lane]     = f2bf2(a0, a1);
        hs[row * PAD2 + 2 * lane + 1] = f2bf2(a2, a3);
    }
    __syncthreads();

    // MMA phase
    int lq = lane >> 2, lr = lane & 3;
    int wr = warp * 16;
    float acc[16][4];
#pragma unroll
    for (int t = 0; t < 16; t++)
#pragma unroll
        for (int q = 0; q < 4; q++) acc[t][q] = 0.f;

#pragma unroll
    for (int kq = 0; kq < 8; kq++) {
        u32 a0 = hs[(wr + lq) * PAD2 + kq * 8 + lr];
        u32 a1 = hs[(wr + lq + 8) * PAD2 + kq * 8 + lr];
        u32 a2 = hs[(wr + lq) * PAD2 + kq * 8 + lr + 4];
        u32 a3 = hs[(wr + lq + 8) * PAD2 + kq * 8 + lr + 4];
#pragma unroll
        for (int t = 0; t < 16; t++) {
            u32 b0 = Ws[(t * 8 + lq) * PAD2 + kq * 8 + lr];
            u32 b1 = Ws[(t * 8 + lq) * PAD2 + kq * 8 + lr + 4];
            mma_bf16(acc[t], a0, a1, a2, a3, b0, b1);
        }
    }

    int r0 = n0 + wr + lq, r1 = r0 + 8;
    float s0 = (r0 < NN) ? g_dinv[r0] : 0.f;
    float s1 = (r1 < NN) ? g_dinv[r1] : 0.f;
#pragma unroll
    for (int t = 0; t < 16; t++) {
        if (r0 < NN) Mout[(size_t)r0 * 64 + t * 4 + lr] = f2bf2(acc[t][0] * s0, acc[t][1] * s0);
        if (r1 < NN) Mout[(size_t)r1 * 64 + t * 4 + lr] = f2bf2(acc[t][2] * s1, acc[t][3] * s1);
    }
}

// ---------------- fused gather + distances + pool (reads g_mb) ----------------
// smem: cs[128][PAD2] | hs[128][PAD2]   (phase 1, 69632 B)
//       dist[128][132] f32              (phase 2, overlays, 67584 B)
//       sx2[128] | sc2[128] | sg[128]   (at offset 69632)
#define DP_SMEM (2 * DD * PAD2 * 4 + 3 * DD * 4)
__global__ void __launch_bounds__(256, 2) k_fused_distpool(const float* __restrict__ cent,
                                                           const int* __restrict__ batch) {
    extern __shared__ u32 sm[];
    u32* cs = sm;                  // [128][PAD2]
    u32* hs = sm + DD * PAD2;      // [128][PAD2]
    float* dist = (float*)sm;      // [128][132] (phase 2 overlay)
    float* sx2 = (float*)(sm + 2 * DD * PAD2);
    float* sc2 = sx2 + DD;
    int*   sg  = (int*)(sc2 + DD);

    int tid = threadIdx.x;
    int warp = tid >> 5, lane = tid & 31;
    int n0 = blockIdx.x * 128;

    if (tid < DD) {
        int n = n0 + tid;
        sg[tid] = (n < NN) ? batch[n] : -1;
    }

    // stage centroids as bf16
    for (int idx = tid; idx < DD * 64; idx += 256) {
        int r = idx >> 6, w = idx & 63;
        u32 cw = 0u;
        if (r < CC) {
            float2 cv = *(const float2*)&cent[r * DD + 2 * w];
            cw = f2bf2(cv.x, cv.y);
        }
        cs[r * PAD2 + w] = cw;
    }

    // gather phase
    const uint2* M2 = (const uint2*)g_mb;
    for (int nn = 0; nn < 16; nn++) {
        int row = warp * 16 + nn;
        int w = n0 + row;
        float a0 = 0.f, a1 = 0.f, a2 = 0.f, a3 = 0.f;
        if (w < NN) gather_node(M2, w, lane, a0, a1, a2, a3);
        hs[row * PAD2 + 2 * lane]     = f2bf2(a0, a1);
        hs[row * PAD2 + 2 * lane + 1] = f2bf2(a2, a3);
    }
    __syncthreads();

    // norms from bf16-rounded values (exact |a-c|^2 composition in fp32)
    if (tid < DD) {
        float sh = 0.f, sc = 0.f;
#pragma unroll 8
        for (int kk = 0; kk < 64; kk++) {
            float2 hv = bf2f(hs[tid * PAD2 + kk]);
            float2 cv = bf2f(cs[tid * PAD2 + kk]);
            sh = fmaf(hv.x, hv.x, sh); sh = fmaf(hv.y, hv.y, sh);
            sc = fmaf(cv.x, cv.x, sc); sc = fmaf(cv.y, cv.y, sc);
        }
        sx2[tid] = sh;
        sc2[tid] = sc;
    }

    // MMA phase
    int lq = lane >> 2, lr = lane & 3;
    int wr = warp * 16;
    float acc[16][4];
#pragma unroll
    for (int t = 0; t < 16; t++)
#pragma unroll
        for (int q = 0; q < 4; q++) acc[t][q] = 0.f;

#pragma unroll
    for (int kq = 0; kq < 8; kq++) {
        u32 a0 = hs[(wr + lq) * PAD2 + kq * 8 + lr];
        u32 a1 = hs[(wr + lq + 8) * PAD2 + kq * 8 + lr];
        u32 a2 = hs[(wr + lq) * PAD2 + kq * 8 + lr + 4];
        u32 a3 = hs[(wr + lq + 8) * PAD2 + kq * 8 + lr + 4];
#pragma unroll
        for (int t = 0; t < 16; t++) {
            u32 b0 = cs[(t * 8 + lq) * PAD2 + kq * 8 + lr];
            u32 b1 = cs[(t * 8 + lq) * PAD2 + kq * 8 + lr + 4];
            mma_bf16(acc[t], a0, a1, a2, a3, b0, b1);
        }
    }
    __syncthreads();   // all cs/hs reads done before dist overlay

    int R0 = wr + lq, R1 = R0 + 8;
    float x0 = sx2[R0], x1 = sx2[R1];
#pragma unroll
    for (int t = 0; t < 16; t++) {
        int c = t * 8 + 2 * lr;
        float c2a = sc2[c], c2b = sc2[c + 1];
        float d0 = sqrtf(fmaxf(x0 + c2a - 2.f * acc[t][0], 0.f) + 1e-12f);
        float d1 = sqrtf(fmaxf(x0 + c2b - 2.f * acc[t][1], 0.f) + 1e-12f);
        float d2 = sqrtf(fmaxf(x1 + c2a - 2.f * acc[t][2], 0.f) + 1e-12f);
        float d3 = sqrtf(fmaxf(x1 + c2b - 2.f * acc[t][3], 0.f) + 1e-12f);
        *(float2*)&dist[R0 * 132 + c] = make_float2(d0, d1);
        *(float2*)&dist[R1 * 132 + c] = make_float2(d2, d3);
    }
    __syncthreads();

    // pooling: 2 threads per column, run-aggregated by graph (batch sorted)
    int c = tid & 127, half = tid >> 7;
    if (c < CC) {
        int rbeg = half * 64, rend = rbeg + 64;
        int cur = -2;
        float s = 0.f;
        for (int r = rbeg; r < rend; r++) {
            int g = sg[r];
            if (g < 0) break;
            float v = dist[r * 132 + c];
            if (g == cur) s += v;
            else {
                if (cur >= 0) atomicAdd(&g_pool[cur * CC + c], s);
                cur = g; s = v;
            }
        }
        if (cur >= 0) atomicAdd(&g_pool[cur * CC + c], s);
    }
}

// ---------------- output ----------------
__global__ void k_out(const float* __restrict__ Wout, const float* __restrict__ bout,
                      float* __restrict__ out) {
    int i = blockIdx.x * blockDim.x + threadIdx.x;
    if (i < GG * KK) {
        int g = i / KK, k = i % KK;
        float inv = 1.0f / fmaxf(g_cnt[g], 1.0f);
        float s = 0.f;
#pragma unroll 4
        for (int c = 0; c < CC; c++) s += g_pool[g * CC + c] * Wout[k * CC + c];
        out[i] = s * inv + bout[k];
    }
}

extern "C" void kernel_launch(void* const* d_in, const int* in_sizes, int n_in,
                              void* d_out, int out_size) {
    const float* x     = (const float*)d_in[0];
    const int*   ei    = (const int*)d_in[1];
    const int*   batch = (const int*)d_in[2];
    const float* We    = (const float*)d_in[3];
    const float* Wc    = (const float*)d_in[4];
    const float* cent  = (const float*)d_in[5];
    const float* Wout  = (const float*)d_in[6];
    const float* bout  = (const float*)d_in[7];
    float* out = (float*)d_out;

    const int* src = ei;
    const int* dst = ei + EE;

    cudaFuncSetAttribute(k_fused_gemm, cudaFuncAttributeMaxDynamicSharedMemorySize, GE_SMEM);
    cudaFuncSetAttribute(k_fused_distpool, cudaFuncAttributeMaxDynamicSharedMemorySize, DP_SMEM);

    const int T = 256;
    int zmax = (NN > GG * CC) ? NN : GG * CC;
    const int GB = (NN + 127) / 128;

    // CSR build + dinv + counts
    k_zero<<<(zmax + T - 1) / T, T>>>();
    k_count<<<(EE + T - 1) / T, T>>>(dst, batch);
    k_scan_part<<<NB, SCB>>>();
    k_scan_bsum<<<1, 256>>>();
    k_scan_add<<<(NN + T - 1) / T, T>>>();
    k_fill<<<(EE + T - 1) / T, T>>>(src, dst);

    // layer 0 messages -> g_mb
    k_fold<<<1, 512>>>(Wc, We);
    k_gemm16<<<NN / 32, T>>>(x);

    // layers 1,2: fused gather+transform (ping-pong via sel)
    k_fused_gemm<<<GB, T, GE_SMEM>>>(Wc + (size_t)1 * DD * DD, 0);  // g_mb -> g_mb2
    k_fused_gemm<<<GB, T, GE_SMEM>>>(Wc + (size_t)2 * DD * DD, 1);  // g_mb2 -> g_mb

    // final: fused gather + distances + pooling (reads g_mb)
    k_fused_distpool<<<GB, T, DP_SMEM>>>(cent, batch);

    k_out<<<(GG * KK + T - 1) / T, T>>>(Wout, bout, out);
}